// round 14
// baseline (speedup 1.0000x reference)
#include <cuda_runtime.h>
#include <cuda_fp16.h>
#include <cstdint>
#include <math.h>

#define S 2048
#define H 2048
#define NH 16
#define D 128
#define NE 8
#define TOPK 4
#define IE 1408
#define IS 5632

// ---------------- fp32 scratch ----------------
static __device__ float g_x2[S * H];
static __device__ float g_h2f[S * H];
static __device__ float g_sm[S * H];
static __device__ float g_sgl[S];
static __device__ float g_rl[S * NE];
static __device__ float g_wsl[NE * S];
static __device__ float g_bqkv[3 * H];
static __device__ int g_cnt[NE];
static __device__ int g_glist[NE * S];
static __device__ int g_slot[S * TOPK];
// ---------------- half scratch ----------------
static __device__ __half g_h1h[S * H];
static __device__ __half g_qkvh[(long long)3 * S * H];
static __device__ __half g_ath[S * H];
static __device__ __half g_h2h[S * H];
static __device__ __half g_uhh[(long long)NE * S * IE];
static __device__ __half g_eoh[(long long)NE * S * H];
static __device__ __half g_ssh[(long long)S * IS];
// half weights
static __device__ __half g_wqkvh[(long long)3 * H * H];
static __device__ __half g_woh[H * H];
static __device__ __half g_egh[(long long)NE * H * IE];
static __device__ __half g_euh[(long long)NE * H * IE];
static __device__ __half g_edh[(long long)NE * IE * H];
static __device__ __half g_sgw[(long long)H * IS];
static __device__ __half g_suw[(long long)H * IS];
static __device__ __half g_sdw[(long long)IS * H];

// ---------------- helpers ----------------
__device__ __forceinline__ uint32_t smem_u32(const void* p) {
    uint32_t a;
    asm("{ .reg .u64 t; cvta.to.shared.u64 t, %1; cvt.u32.u64 %0, t; }" : "=r"(a) : "l"(p));
    return a;
}
__device__ __forceinline__ void cp16(uint32_t dst, const void* src) {
    asm volatile("cp.async.cg.shared.global [%0], [%1], 16;" :: "r"(dst), "l"(src));
}
#define CP_COMMIT() asm volatile("cp.async.commit_group;" ::: "memory")
#define CP_WAIT2() asm volatile("cp.async.wait_group 2;" ::: "memory")
#define CP_WAIT1() asm volatile("cp.async.wait_group 1;" ::: "memory")
#define CP_WAIT0() asm volatile("cp.async.wait_group 0;" ::: "memory")

__device__ __forceinline__ void ldsm_x4(uint32_t* r, uint32_t addr) {
    asm volatile("ldmatrix.sync.aligned.m8n8.x4.shared.b16 {%0,%1,%2,%3}, [%4];"
        : "=r"(r[0]), "=r"(r[1]), "=r"(r[2]), "=r"(r[3]) : "r"(addr));
}
__device__ __forceinline__ void ldsm_x4_t(uint32_t* r, uint32_t addr) {
    asm volatile("ldmatrix.sync.aligned.m8n8.x4.trans.shared.b16 {%0,%1,%2,%3}, [%4];"
        : "=r"(r[0]), "=r"(r[1]), "=r"(r[2]), "=r"(r[3]) : "r"(addr));
}
__device__ __forceinline__ void mma_f16(float* d, const uint32_t* a, const uint32_t* b) {
    asm volatile(
        "mma.sync.aligned.m16n8k16.row.col.f32.f16.f16.f32 "
        "{%0,%1,%2,%3}, {%4,%5,%6,%7}, {%8,%9}, {%0,%1,%2,%3};"
        : "+f"(d[0]), "+f"(d[1]), "+f"(d[2]), "+f"(d[3])
        : "r"(a[0]), "r"(a[1]), "r"(a[2]), "r"(a[3]), "r"(b[0]), "r"(b[1]));
}
__device__ __forceinline__ uint32_t pack_h2(float a, float b) {
    half2 h = __floats2half2_rn(a, b);
    return *(uint32_t*)&h;
}
__device__ __forceinline__ float siluf(float x) { return x / (1.f + expf(-x)); }

// ---------------- fp16 mma GEMM (128x128 CTA, 8 warps 64x32, K-stage 32, 4-deep pipe,
//                  ONE __syncthreads per stage; optional dual-pass gate+up) -------------
// EPI: 0 none, 1 +bias[z*2048+col], 2 +resid, 4 acc*X[z*S+row].
// OUTH: half out. IDX: 0 none, 1 gather A via glist+bound, 2 bound only.
// ROPE: for z<2, rotate (d,d+64) per head in-epilogue. DUAL: pass1 B (gate), pass2 B2
// (up), output silu(gate)*up.
#define A_ELT 5120
#define B_ELT 4352
#define SMEM_BASE (4 * (A_ELT + B_ELT) * 2)
#define SMEM_DUAL (SMEM_BASE + 256 * 32 * 4)

template <int EPI, bool OUTH, int IDX, bool ROPE, bool DUAL>
__global__ void __launch_bounds__(256, 2)
hgemm(const __half* __restrict__ A, const __half* __restrict__ B,
      const __half* __restrict__ B2,
      void* __restrict__ Cv, const float* __restrict__ X,
      const int* __restrict__ glist, const int* __restrict__ cnt,
      int K, int lda, int ldb, int ldc,
      long long sA, long long sB, long long sC) {
    int cbound = 0x7fffffff;
    if (IDX) {
        cbound = cnt[blockIdx.z];
        if ((int)blockIdx.y * 128 >= cbound) return;
    }
    extern __shared__ __half dsm[];
    __half* const AS = dsm;
    __half* const BS = dsm + 4 * A_ELT;
    __shared__ float s_inv[64];

    int tid = threadIdx.x, lane = tid & 31, wid = tid >> 5;
    int row0 = blockIdx.y * 128, col0 = blockIdx.x * 128;

    if (ROPE && tid < 64)
        s_inv[tid] = (float)exp(-((double)(2 * tid) / 128.0) * 13.815510557964274);

    A += (long long)blockIdx.z * sA;
    if (IDX != 1) A += (long long)row0 * lda;
    const __half* Bp = B + (long long)blockIdx.z * sB + col0;
    const __half* B2p = DUAL ? B2 + (long long)blockIdx.z * sB + col0 : (const __half*)0;

    int nstg = K >> 5;

    int arow = tid >> 2, acol = (tid & 3) * 8;
    int nrow = tid >> 4, ncol = (tid & 15) * 8;

    const __half* aptr[2];
#pragma unroll
    for (int i = 0; i < 2; i++) {
        int r = arow + i * 64;
        if (IDX == 1) {
            int gr = row0 + r;
            int ti = glist[blockIdx.z * S + (gr < cbound ? gr : 0)];
            aptr[i] = A + (long long)ti * lda;
        } else {
            aptr[i] = A + (long long)r * lda;
        }
    }

    const __half* Bcur = Bp;
    auto fill = [&](int s, int k0) {
        __half* ad = AS + s * A_ELT;
        __half* bd = BS + s * B_ELT;
#pragma unroll
        for (int i = 0; i < 2; i++)
            cp16(smem_u32(ad + (arow + i * 64) * 40 + acol), aptr[i] + k0 + acol);
#pragma unroll
        for (int i = 0; i < 2; i++)
            cp16(smem_u32(bd + (nrow + i * 16) * 136 + ncol),
                 Bcur + (long long)(k0 + nrow + i * 16) * ldb + ncol);
        CP_COMMIT();
    };

    float acc[4][4][4];
#pragma unroll
    for (int i = 0; i < 4; i++)
#pragma unroll
        for (int j = 0; j < 4; j++)
#pragma unroll
            for (int u = 0; u < 4; u++) acc[i][j][u] = 0.f;

    int wm = (wid & 1) * 64, wn = (wid >> 1) * 32;
    int fr = lane >> 2, fc = lane & 3;
    int l15 = lane & 15, lhi = (lane >> 4) << 3;

    uint32_t* stash = (uint32_t*)(dsm + SMEM_BASE / 2) + tid * 32;

    int npass = DUAL ? 2 : 1;
    for (int pass = 0; pass < npass; pass++) {
        if (pass == 1) Bcur = B2p;
        fill(0, 0);
        if (nstg > 1) fill(1, 32);
        if (nstg > 2) fill(2, 64);
        for (int t = 0; t < nstg; t++) {
            if (t + 2 < nstg) CP_WAIT2();
            else if (t + 1 < nstg) CP_WAIT1();
            else CP_WAIT0();
            __syncthreads();
            if (t + 3 < nstg) fill((t + 3) & 3, (t + 3) * 32);
            const __half* as = AS + (t & 3) * A_ELT;
            const __half* bs = BS + (t & 3) * B_ELT;
#pragma unroll
            for (int kk = 0; kk < 32; kk += 16) {
                uint32_t af[4][4];
#pragma unroll
                for (int mt = 0; mt < 4; mt++)
                    ldsm_x4(af[mt], smem_u32(as + (wm + mt * 16 + l15) * 40 + kk + lhi));
                uint32_t bf[4][2];
#pragma unroll
                for (int p = 0; p < 2; p++) {
                    uint32_t tmp[4];
                    ldsm_x4_t(tmp, smem_u32(bs + (kk + l15) * 136 + wn + p * 16 + lhi));
                    bf[2 * p][0] = tmp[0]; bf[2 * p][1] = tmp[1];
                    bf[2 * p + 1][0] = tmp[2]; bf[2 * p + 1][1] = tmp[3];
                }
#pragma unroll
                for (int mt = 0; mt < 4; mt++)
#pragma unroll
                    for (int nt = 0; nt < 4; nt++) mma_f16(acc[mt][nt], af[mt], bf[nt]);
            }
        }
        if (DUAL && pass == 0) {
#pragma unroll
            for (int mt = 0; mt < 4; mt++)
#pragma unroll
                for (int nt = 0; nt < 4; nt++) {
                    stash[(mt * 4 + nt) * 2] = pack_h2(acc[mt][nt][0], acc[mt][nt][1]);
                    stash[(mt * 4 + nt) * 2 + 1] = pack_h2(acc[mt][nt][2], acc[mt][nt][3]);
                    acc[mt][nt][0] = acc[mt][nt][1] = acc[mt][nt][2] = acc[mt][nt][3] = 0.f;
                }
            __syncthreads();
        }
    }

    bool doRope = ROPE && (blockIdx.z < 2);
    if (doRope) __syncthreads();

#pragma unroll
    for (int mt = 0; mt < 4; mt++) {
        int m = row0 + wm + mt * 16 + fr;
        float w0 = 1.f, w1 = 1.f;
        if (EPI == 4) {
            bool ok0 = (!IDX || m < cbound), ok1 = (!IDX || m + 8 < cbound);
            w0 = ok0 ? X[(long long)blockIdx.z * S + m] : 0.f;
            w1 = ok1 ? X[(long long)blockIdx.z * S + m + 8] : 0.f;
        }
#pragma unroll
        for (int nt = 0; nt < 4; nt++) {
            int nl = wn + nt * 8 + fc * 2;
            int n = col0 + nl;
            float2 v0 = make_float2(acc[mt][nt][0], acc[mt][nt][1]);
            float2 v1 = make_float2(acc[mt][nt][2], acc[mt][nt][3]);
            if (EPI == 1) {
                const float* bz = X + (long long)blockIdx.z * 2048;
                v0.x += bz[n]; v0.y += bz[n + 1];
                v1.x += bz[n]; v1.y += bz[n + 1];
            }
            if (EPI == 2) {
                const float2 r0 = *(const float2*)&X[(long long)m * ldc + n];
                const float2 r1 = *(const float2*)&X[(long long)(m + 8) * ldc + n];
                v0.x += r0.x; v0.y += r0.y;
                v1.x += r1.x; v1.y += r1.y;
            }
            if (DUAL) {
                half2 g0 = *(half2*)&stash[(mt * 4 + nt) * 2];
                half2 g1 = *(half2*)&stash[(mt * 4 + nt) * 2 + 1];
                v0.x *= siluf(__half2float(g0.x));
                v0.y *= siluf(__half2float(g0.y));
                v1.x *= siluf(__half2float(g1.x));
                v1.y *= siluf(__half2float(g1.y));
            }
            if (EPI == 4) {
                v0.x *= w0; v0.y *= w0;
                v1.x *= w1; v1.y *= w1;
            }
            if (doRope) {
                int rl0 = wm + mt * 16 + fr;
                *(half2*)&dsm[rl0 * 136 + nl] = __floats2half2_rn(v0.x, v0.y);
                *(half2*)&dsm[(rl0 + 8) * 136 + nl] = __floats2half2_rn(v1.x, v1.y);
            } else if (OUTH) {
                __half* C = (__half*)Cv + (long long)blockIdx.z * sC;
                if (!IDX || m < cbound)
                    *(half2*)&C[(long long)m * ldc + n] = __floats2half2_rn(v0.x, v0.y);
                if (!IDX || m + 8 < cbound)
                    *(half2*)&C[(long long)(m + 8) * ldc + n] = __floats2half2_rn(v1.x, v1.y);
            } else {
                float* C = (float*)Cv + (long long)blockIdx.z * sC;
                if (!IDX || m < cbound)
                    *(float2*)&C[(long long)m * ldc + n] = v0;
                if (!IDX || m + 8 < cbound)
                    *(float2*)&C[(long long)(m + 8) * ldc + n] = v1;
            }
        }
    }

    if (doRope) {
        __syncthreads();
        __half* C = (__half*)Cv + (long long)blockIdx.z * sC;
        for (int it = tid; it < 128 * 64; it += 256) {
            int row = it >> 6, d = it & 63;
            int sg = row0 + row;
            float ang = (float)sg * s_inv[d];
            float cc = cosf(ang), ssn = sinf(ang);
            float a = __half2float(dsm[row * 136 + d]);
            float b = __half2float(dsm[row * 136 + d + 64]);
            C[(long long)sg * ldc + col0 + d] = __float2half_rn(a * cc - b * ssn);
            C[(long long)sg * ldc + col0 + d + 64] = __float2half_rn(b * cc + a * ssn);
        }
    }
}

// ---------------- flash attention ----------------
#define FSC 0.12751744f
__global__ void __launch_bounds__(256, 1)
flash_kernel(const __half* __restrict__ Q, const __half* __restrict__ K,
             const __half* __restrict__ V, __half* __restrict__ O) {
    int qb = 15 - (int)blockIdx.x;
    int h = blockIdx.y;
    extern __shared__ __half fsm[];
    __half* Qs = fsm;
    __half* Ks = fsm + 128 * 136;
    __half* Vs = Ks + 2 * 128 * 136;

    int tid = threadIdx.x, lane = tid & 31, wid = tid >> 5;
    int fr = lane >> 2, fc = lane & 3;
    int l15 = lane & 15, lhi = (lane >> 4) << 3;
    int wm = wid * 16;

    const __half* qg = Q + (long long)(qb * 128) * H + h * D;
    const __half* kg = K + h * D;
    const __half* vg = V + h * D;

    int lr = tid >> 1, lc = (tid & 1) * 64;
#pragma unroll
    for (int j = 0; j < 8; j++)
        cp16(smem_u32(Qs + lr * 136 + lc + j * 8), qg + (long long)lr * H + lc + j * 8);

    auto loadKV = [&](int buf, int kt) {
        const __half* ks = kg + (long long)(kt * 128) * H;
        const __half* vs = vg + (long long)(kt * 128) * H;
        __half* kd = Ks + buf * (128 * 136);
        __half* vd = Vs + buf * (128 * 136);
#pragma unroll
        for (int j = 0; j < 8; j++) {
            cp16(smem_u32(kd + lr * 136 + lc + j * 8), ks + (long long)lr * H + lc + j * 8);
            cp16(smem_u32(vd + lr * 136 + lc + j * 8), vs + (long long)lr * H + lc + j * 8);
        }
    };
    loadKV(0, 0); CP_COMMIT();

    float oacc[16][4];
#pragma unroll
    for (int i = 0; i < 16; i++)
#pragma unroll
        for (int u = 0; u < 4; u++) oacc[i][u] = 0.f;
    float m0 = -1e30f, m1 = -1e30f, l0 = 0.f, l1 = 0.f;

    int ntile = qb + 1;
    for (int t = 0; t < ntile; t++) {
        if (t + 1 < ntile) { loadKV((t + 1) & 1, t + 1); CP_COMMIT(); CP_WAIT1(); }
        else CP_WAIT0();
        __syncthreads();
        const __half* kb = Ks + (t & 1) * (128 * 136);
        const __half* vb = Vs + (t & 1) * (128 * 136);

        float s[16][4];
#pragma unroll
        for (int i = 0; i < 16; i++)
#pragma unroll
            for (int u = 0; u < 4; u++) s[i][u] = 0.f;

#pragma unroll
        for (int kk = 0; kk < 8; kk++) {
            uint32_t aq[4];
            ldsm_x4(aq, smem_u32(Qs + (wm + l15) * 136 + kk * 16 + lhi));
#pragma unroll
            for (int nt = 0; nt < 16; nt++) {
                uint32_t bk[2];
                bk[0] = *(const uint32_t*)(kb + (nt * 8 + fr) * 136 + kk * 16 + 2 * fc);
                bk[1] = *(const uint32_t*)(kb + (nt * 8 + fr) * 136 + kk * 16 + 2 * fc + 8);
                mma_f16(s[nt], aq, bk);
            }
        }

        if (t == qb) {
            int r0 = wm + fr, r1 = r0 + 8;
#pragma unroll
            for (int nt = 0; nt < 16; nt++) {
                int c0 = nt * 8 + 2 * fc;
                if (c0 > r0) s[nt][0] = -1e30f;
                if (c0 + 1 > r0) s[nt][1] = -1e30f;
                if (c0 > r1) s[nt][2] = -1e30f;
                if (c0 + 1 > r1) s[nt][3] = -1e30f;
            }
        }

        float mx0 = -1e30f, mx1 = -1e30f;
#pragma unroll
        for (int nt = 0; nt < 16; nt++) {
            mx0 = fmaxf(mx0, fmaxf(s[nt][0], s[nt][1]));
            mx1 = fmaxf(mx1, fmaxf(s[nt][2], s[nt][3]));
        }
        mx0 = fmaxf(mx0, __shfl_xor_sync(0xffffffffu, mx0, 1));
        mx0 = fmaxf(mx0, __shfl_xor_sync(0xffffffffu, mx0, 2));
        mx1 = fmaxf(mx1, __shfl_xor_sync(0xffffffffu, mx1, 1));
        mx1 = fmaxf(mx1, __shfl_xor_sync(0xffffffffu, mx1, 2));

        float mn0 = fmaxf(m0, mx0), mn1 = fmaxf(m1, mx1);
        float rs0 = exp2f((m0 - mn0) * FSC), rs1 = exp2f((m1 - mn1) * FSC);
        m0 = mn0; m1 = mn1;

        float sm0 = 0.f, sm1 = 0.f;
#pragma unroll
        for (int nt = 0; nt < 16; nt++) {
            s[nt][0] = exp2f((s[nt][0] - m0) * FSC);
            s[nt][1] = exp2f((s[nt][1] - m0) * FSC);
            s[nt][2] = exp2f((s[nt][2] - m1) * FSC);
            s[nt][3] = exp2f((s[nt][3] - m1) * FSC);
            sm0 += s[nt][0] + s[nt][1];
            sm1 += s[nt][2] + s[nt][3];
        }
        sm0 += __shfl_xor_sync(0xffffffffu, sm0, 1);
        sm0 += __shfl_xor_sync(0xffffffffu, sm0, 2);
        sm1 += __shfl_xor_sync(0xffffffffu, sm1, 1);
        sm1 += __shfl_xor_sync(0xffffffffu, sm1, 2);
        l0 = l0 * rs0 + sm0;
        l1 = l1 * rs1 + sm1;
#pragma unroll
        for (int nt = 0; nt < 16; nt++) {
            oacc[nt][0] *= rs0; oacc[nt][1] *= rs0;
            oacc[nt][2] *= rs1; oacc[nt][3] *= rs1;
        }

#pragma unroll
        for (int kc = 0; kc < 8; kc++) {
            uint32_t pa[4];
            pa[0] = pack_h2(s[2 * kc][0], s[2 * kc][1]);
            pa[1] = pack_h2(s[2 * kc][2], s[2 * kc][3]);
            pa[2] = pack_h2(s[2 * kc + 1][0], s[2 * kc + 1][1]);
            pa[3] = pack_h2(s[2 * kc + 1][2], s[2 * kc + 1][3]);
#pragma unroll
            for (int p = 0; p < 8; p++) {
                uint32_t tmp[4];
                ldsm_x4_t(tmp, smem_u32(vb + (kc * 16 + l15) * 136 + p * 16 + lhi));
                mma_f16(oacc[2 * p], pa, tmp);
                mma_f16(oacc[2 * p + 1], pa, tmp + 2);
            }
        }
        __syncthreads();
    }

    float inv0 = 1.f / l0, inv1 = 1.f / l1;
    __half* og = O + (long long)(qb * 128) * H + h * D;
    int r0 = wm + fr, r1 = r0 + 8;
#pragma unroll
    for (int nt = 0; nt < 16; nt++) {
        int col = nt * 8 + 2 * fc;
        *(half2*)(og + (long long)r0 * H + col) =
            __floats2half2_rn(oacc[nt][0] * inv0, oacc[nt][1] * inv0);
        *(half2*)(og + (long long)r1 * H + col) =
            __floats2half2_rn(oacc[nt][2] * inv1, oacc[nt][3] * inv1);
    }
}
#define FLASH_SMEM ((128 + 256 + 256) * 136 * 2)

// ---------------- fp32 -> fp16 (2x float4 per thread per iter) ----------------
__global__ void f2h_kernel(const float* __restrict__ in, __half* __restrict__ out, long long n) {
    long long i = ((long long)blockIdx.x * 256 + threadIdx.x) * 8;
    long long stride = (long long)gridDim.x * 2048;
    for (; i + 7 < n; i += stride) {
        float4 a = *(const float4*)&in[i];
        float4 b = *(const float4*)&in[i + 4];
        *(half2*)&out[i] = __floats2half2_rn(a.x, a.y);
        *(half2*)&out[i + 2] = __floats2half2_rn(a.z, a.w);
        *(half2*)&out[i + 4] = __floats2half2_rn(b.x, b.y);
        *(half2*)&out[i + 6] = __floats2half2_rn(b.z, b.w);
    }
}
static inline unsigned f2h_grid(long long n) {
    long long g = (n / 8 + 255) / 256;
    return (unsigned)(g > 4096 ? 4096 : g);
}

// ---------------- pack 3 bias vectors ----------------
__global__ void bcopy_kernel(const float* a, const float* b, const float* c, float* o) {
    int i = blockIdx.x * 1024 + threadIdx.x;
    const float* src[3] = {a, b, c};
    o[i] = src[i >> 11][i & 2047];
}

// ---------------- RMSNorm ----------------
__global__ void rmsnorm_kernel(const float* __restrict__ x, const float* __restrict__ w,
                               __half* __restrict__ oh, float* __restrict__ of,
                               int* __restrict__ zcnt) {
    int s = blockIdx.x;
    if (zcnt && s == 0 && threadIdx.x < NE) zcnt[threadIdx.x] = 0;
    const float* xr = x + (long long)s * H;
    int tid = threadIdx.x;
    float ss = 0.f;
    for (int i = tid; i < H; i += 256) { float v = xr[i]; ss += v * v; }
    __shared__ float sh[8];
#pragma unroll
    for (int off = 16; off; off >>= 1) ss += __shfl_xor_sync(0xffffffffu, ss, off);
    if ((tid & 31) == 0) sh[tid >> 5] = ss;
    __syncthreads();
    ss = sh[tid & 7];
#pragma unroll
    for (int off = 4; off; off >>= 1) ss += __shfl_xor_sync(0xffffffffu, ss, off);
    float inv = rsqrtf(ss / (float)H + 1e-6f);
    for (int i = tid; i < H; i += 256) {
        float v = w[i] * xr[i] * inv;
        oh[(long long)s * H + i] = __float2half_rn(v);
        if (of) of[(long long)s * H + i] = v;
    }
}

// ---------------- router + top-k compaction ----------------
__global__ void router_kernel(const float* __restrict__ h2, const float* __restrict__ gw,
                              const float* __restrict__ sgate, float* __restrict__ rl,
                              float* __restrict__ sgl, int* __restrict__ cnt,
                              int* __restrict__ glist, int* __restrict__ slot,
                              float* __restrict__ wsl) {
    int s = blockIdx.x;
    int tid = threadIdx.x;
    const float* hr = h2 + (long long)s * H;
    float acc[9];
#pragma unroll
    for (int j = 0; j < 9; j++) acc[j] = 0.f;
    for (int i = tid; i < H; i += 256) {
        float hv = hr[i];
        const float* gr = gw + (long long)i * NE;
#pragma unroll
        for (int e = 0; e < NE; e++) acc[e] += hv * gr[e];
        acc[8] += hv * sgate[i];
    }
    __shared__ float sh[8][9];
    int warp = tid >> 5, lane = tid & 31;
#pragma unroll
    for (int j = 0; j < 9; j++) {
        float v = acc[j];
#pragma unroll
        for (int o = 16; o; o >>= 1) v += __shfl_xor_sync(0xffffffffu, v, o);
        if (lane == 0) sh[warp][j] = v;
    }
    __syncthreads();
    if (tid == 0) {
        float t[9];
#pragma unroll
        for (int j = 0; j < 9; j++) {
            float v = 0.f;
            for (int wi = 0; wi < 8; wi++) v += sh[wi][j];
            t[j] = v;
        }
        float mx = t[0];
        for (int e = 1; e < NE; e++) mx = fmaxf(mx, t[e]);
        float p[NE], sum = 0.f;
        for (int e = 0; e < NE; e++) { p[e] = expf(t[e] - mx); sum += p[e]; }
        for (int e = 0; e < NE; e++) p[e] /= sum;
        for (int kI = 0; kI < TOPK; kI++) {
            int bi = 0;
            float bv = p[0];
            for (int e = 1; e < NE; e++)
                if (p[e] > bv) { bv = p[e]; bi = e; }
            int pos = atomicAdd(&cnt[bi], 1);
            glist[bi * S + pos] = s;
            slot[s * TOPK + kI] = bi * S + pos;
            wsl[bi * S + pos] = bv;
            p[bi] = -1.f;
        }
        for (int e = 0; e < NE; e++) rl[s * NE + e] = t[e];
        sgl[s] = t[8];
    }
}

// ---------------- final combine ----------------
__global__ void final_kernel(const float* __restrict__ x2, const __half* __restrict__ eoh,
                             const int* __restrict__ slot,
                             const float* __restrict__ sm, const float* __restrict__ sgl,
                             float* __restrict__ out) {
    int i = blockIdx.x * 256 + threadIdx.x;
    int s = i >> 11, c = i & 2047;
    float mo = 0.f;
#pragma unroll
    for (int kI = 0; kI < TOPK; kI++)
        mo += __half2float(eoh[(long long)slot[s * TOPK + kI] * H + c]);
    float gg = 1.f / (1.f + expf(-sgl[s]));
    out[i] = x2[i] + mo + gg * sm[i];
}

// ---------------- host ----------------
extern "C" void kernel_launch(void* const* d_in, const int* in_sizes, int n_in,
                              void* d_out, int out_size) {
    const float* x = (const float*)d_in[0];
    const float* ln1 = (const float*)d_in[1];
    const float* ln2 = (const float*)d_in[2];
    const float* wq = (const float*)d_in[3];
    const float* bq = (const float*)d_in[4];
    const float* wk = (const float*)d_in[5];
    const float* bk = (const float*)d_in[6];
    const float* wv = (const float*)d_in[7];
    const float* bv = (const float*)d_in[8];
    const float* wo = (const float*)d_in[9];
    const float* gw = (const float*)d_in[10];
    const float* eg = (const float*)d_in[11];
    const float* eu = (const float*)d_in[12];
    const float* ed = (const float*)d_in[13];
    const float* sg = (const float*)d_in[14];
    const float* su = (const float*)d_in[15];
    const float* sd = (const float*)d_in[16];
    const float* sgate = (const float*)d_in[17];
    float* out = (float*)d_out;

    float *x2, *h2f, *sm, *sgl, *rls, *wsl, *bqkv;
    int *cnt, *glist, *slot;
    __half *h1h, *qkvh, *ath, *h2h, *uhh, *eoh, *ssh;
    __half *wqkvh, *woh, *egh, *euh, *edh, *sgw, *suw, *sdw;
    cudaGetSymbolAddress((void**)&x2, g_x2);
    cudaGetSymbolAddress((void**)&h2f, g_h2f);
    cudaGetSymbolAddress((void**)&sm, g_sm);
    cudaGetSymbolAddress((void**)&sgl, g_sgl);
    cudaGetSymbolAddress((void**)&rls, g_rl);
    cudaGetSymbolAddress((void**)&wsl, g_wsl);
    cudaGetSymbolAddress((void**)&bqkv, g_bqkv);
    cudaGetSymbolAddress((void**)&cnt, g_cnt);
    cudaGetSymbolAddress((void**)&glist, g_glist);
    cudaGetSymbolAddress((void**)&slot, g_slot);
    cudaGetSymbolAddress((void**)&h1h, g_h1h);
    cudaGetSymbolAddress((void**)&qkvh, g_qkvh);
    cudaGetSymbolAddress((void**)&ath, g_ath);
    cudaGetSymbolAddress((void**)&h2h, g_h2h);
    cudaGetSymbolAddress((void**)&uhh, g_uhh);
    cudaGetSymbolAddress((void**)&eoh, g_eoh);
    cudaGetSymbolAddress((void**)&ssh, g_ssh);
    cudaGetSymbolAddress((void**)&wqkvh, g_wqkvh);
    cudaGetSymbolAddress((void**)&woh, g_woh);
    cudaGetSymbolAddress((void**)&egh, g_egh);
    cudaGetSymbolAddress((void**)&euh, g_euh);
    cudaGetSymbolAddress((void**)&edh, g_edh);
    cudaGetSymbolAddress((void**)&sgw, g_sgw);
    cudaGetSymbolAddress((void**)&suw, g_suw);
    cudaGetSymbolAddress((void**)&sdw, g_sdw);

    __half* qh = qkvh;
    __half* kh = qkvh + (long long)S * H;
    __half* vh = qkvh + (long long)2 * S * H;

    cudaFuncSetAttribute(flash_kernel, cudaFuncAttributeMaxDynamicSharedMemorySize, FLASH_SMEM);
    cudaFuncSetAttribute(hgemm<1, true, 0, true, false>, cudaFuncAttributeMaxDynamicSharedMemorySize, SMEM_BASE);
    cudaFuncSetAttribute(hgemm<2, false, 0, false, false>, cudaFuncAttributeMaxDynamicSharedMemorySize, SMEM_BASE);
    cudaFuncSetAttribute(hgemm<0, true, 1, false, true>, cudaFuncAttributeMaxDynamicSharedMemorySize, SMEM_DUAL);
    cudaFuncSetAttribute(hgemm<4, true, 2, false, false>, cudaFuncAttributeMaxDynamicSharedMemorySize, SMEM_BASE);
    cudaFuncSetAttribute(hgemm<0, true, 0, false, true>, cudaFuncAttributeMaxDynamicSharedMemorySize, SMEM_DUAL);
    cudaFuncSetAttribute(hgemm<0, false, 0, false, false>, cudaFuncAttributeMaxDynamicSharedMemorySize, SMEM_BASE);

    static cudaStream_t s2 = 0, s3 = 0;
    static cudaEvent_t evFork = 0, evW0 = 0, evWm = 0, evWd = 0, evWs = 0, evW = 0,
                       evH2 = 0, evSh = 0, evN = 0;
    if (!s2) {
        cudaStreamCreateWithFlags(&s2, cudaStreamNonBlocking);
        cudaStreamCreateWithFlags(&s3, cudaStreamNonBlocking);
        cudaEventCreateWithFlags(&evFork, cudaEventDisableTiming);
        cudaEventCreateWithFlags(&evW0, cudaEventDisableTiming);
        cudaEventCreateWithFlags(&evWm, cudaEventDisableTiming);
        cudaEventCreateWithFlags(&evWd, cudaEventDisableTiming);
        cudaEventCreateWithFlags(&evWs, cudaEventDisableTiming);
        cudaEventCreateWithFlags(&evW, cudaEventDisableTiming);
        cudaEventCreateWithFlags(&evH2, cudaEventDisableTiming);
        cudaEventCreateWithFlags(&evSh, cudaEventDisableTiming);
        cudaEventCreateWithFlags(&evN, cudaEventDisableTiming);
    }

    float* rl_dst = (out_size >= S * H + S * NE) ? (out + (size_t)S * H) : rls;

    // ---- fork conversion stream, ordered by consumer time ----
    cudaEventRecord(evFork, 0);
    cudaStreamWaitEvent(s2, evFork, 0);
    bcopy_kernel<<<6, 1024, 0, s2>>>(bq, bk, bv, bqkv);
    f2h_kernel<<<f2h_grid((long long)H * H), 256, 0, s2>>>(wq, wqkvh, (long long)H * H);
    f2h_kernel<<<f2h_grid((long long)H * H), 256, 0, s2>>>(wk, wqkvh + (long long)H * H, (long long)H * H);
    f2h_kernel<<<f2h_grid((long long)H * H), 256, 0, s2>>>(wv, wqkvh + (long long)2 * H * H, (long long)H * H);
    cudaEventRecord(evW0, s2);
    f2h_kernel<<<f2h_grid((long long)H * H), 256, 0, s2>>>(wo, woh, (long long)H * H);
    f2h_kernel<<<4096, 256, 0, s2>>>(eg, egh, (long long)NE * H * IE);
    f2h_kernel<<<4096, 256, 0, s2>>>(eu, euh, (long long)NE * H * IE);
    cudaEventRecord(evWm, s2);
    f2h_kernel<<<4096, 256, 0, s2>>>(ed, edh, (long long)NE * IE * H);
    cudaEventRecord(evWd, s2);
    f2h_kernel<<<4096, 256, 0, s2>>>(sg, sgw, (long long)H * IS);
    f2h_kernel<<<4096, 256, 0, s2>>>(su, suw, (long long)H * IS);
    cudaEventRecord(evWs, s2);
    f2h_kernel<<<4096, 256, 0, s2>>>(sd, sdw, (long long)IS * H);
    cudaEventRecord(evW, s2);

    // ---- rmsnorm1 on s3 concurrent with f2h ----
    cudaStreamWaitEvent(s3, evFork, 0);
    rmsnorm_kernel<<<S, 256, 0, s3>>>(x, ln1, h1h, (float*)0, (int*)0);
    cudaEventRecord(evN, s3);

    // ---- main stream: attention path ----
    cudaStreamWaitEvent(0, evW0, 0);
    cudaStreamWaitEvent(0, evN, 0);
    hgemm<1, true, 0, true, false><<<dim3(16, 16, 3), 256, SMEM_BASE>>>(
        h1h, wqkvh, (const __half*)0, qkvh, bqkv, 0, 0,
        H, H, H, H, 0LL, (long long)H * H, (long long)S * H);
    flash_kernel<<<dim3(16, NH), 256, FLASH_SMEM>>>(qh, kh, vh, ath);
    hgemm<2, false, 0, false, false><<<dim3(16, 16, 1), 256, SMEM_BASE>>>(
        ath, woh, (const __half*)0, x2, x, 0, 0, H, H, H, H, 0, 0, 0);
    rmsnorm_kernel<<<S, 256>>>(x2, ln2, h2h, h2f, cnt);
    cudaEventRecord(evH2, 0);
    router_kernel<<<S, 256>>>(h2f, gw, sgate, rl_dst, sgl, cnt, glist, slot, wsl);

    // ---- stream s3: shared MLP branch (dual gate+up, then down) ----
    cudaStreamWaitEvent(s3, evH2, 0);
    cudaStreamWaitEvent(s3, evWs, 0);
    hgemm<0, true, 0, false, true><<<dim3(IS / 128, 16, 1), 256, SMEM_DUAL, s3>>>(
        h2h, sgw, suw, ssh, (const float*)0, 0, 0, H, H, IS, IS, 0, 0, 0);
    cudaStreamWaitEvent(s3, evW, 0);
    hgemm<0, false, 0, false, false><<<dim3(16, 16, 1), 256, SMEM_BASE, s3>>>(
        ssh, sdw, (const __half*)0, sm, (const float*)0, 0, 0, IS, IS, H, H, 0, 0, 0);
    cudaEventRecord(evSh, s3);

    // ---- main stream: sparse MoE branch (dual gate+up, then weighted down) ----
    cudaStreamWaitEvent(0, evWm, 0);
    hgemm<0, true, 1, false, true><<<dim3(IE / 128, 16, NE), 256, SMEM_DUAL>>>(
        h2h, egh, euh, uhh, (const float*)0, glist, cnt,
        H, H, IE, IE, 0LL, (long long)H * IE, (long long)S * IE);
    cudaStreamWaitEvent(0, evWd, 0);
    hgemm<4, true, 2, false, false><<<dim3(16, 16, NE), 256, SMEM_BASE>>>(
        uhh, edh, (const __half*)0, eoh, wsl, (const int*)0, cnt,
        IE, IE, H, H, (long long)S * IE, (long long)IE * H, (long long)S * H);

    // ---- join + combine ----
    cudaStreamWaitEvent(0, evSh, 0);
    final_kernel<<<(S * H) / 256, 256>>>(x2, eoh, slot, sm, sgl, out);
}

// round 15
// speedup vs baseline: 1.0048x; 1.0048x over previous
#include <cuda_runtime.h>
#include <cuda_fp16.h>
#include <cstdint>
#include <math.h>

#define S 2048
#define H 2048
#define NH 16
#define D 128
#define NE 8
#define TOPK 4
#define IE 1408
#define IS 5632

// ---------------- fp32 scratch ----------------
static __device__ float g_x2[S * H];
static __device__ float g_h2f[S * H];
static __device__ float g_sm[S * H];
static __device__ float g_sgl[S];
static __device__ float g_rl[S * NE];
static __device__ float g_wsl[NE * S];
static __device__ float g_bqkv[3 * H];
static __device__ int g_cnt[NE];
static __device__ int g_glist[NE * S];
static __device__ int g_slot[S * TOPK];
// ---------------- half scratch ----------------
static __device__ __half g_h1h[S * H];
static __device__ __half g_qkvh[(long long)3 * S * H];
static __device__ __half g_ath[S * H];
static __device__ __half g_h2h[S * H];
static __device__ __half g_uhh[(long long)NE * S * IE];
static __device__ __half g_eoh[(long long)NE * S * H];
static __device__ __half g_ssh[(long long)S * IS];
// half weights
static __device__ __half g_wqkvh[(long long)3 * H * H];
static __device__ __half g_woh[H * H];
static __device__ __half g_egh[(long long)NE * H * IE];
static __device__ __half g_euh[(long long)NE * H * IE];
static __device__ __half g_edh[(long long)NE * IE * H];
static __device__ __half g_sgw[(long long)H * IS];
static __device__ __half g_suw[(long long)H * IS];
static __device__ __half g_sdw[(long long)IS * H];

// ---------------- helpers ----------------
__device__ __forceinline__ uint32_t smem_u32(const void* p) {
    uint32_t a;
    asm("{ .reg .u64 t; cvta.to.shared.u64 t, %1; cvt.u32.u64 %0, t; }" : "=r"(a) : "l"(p));
    return a;
}
__device__ __forceinline__ void cp16(uint32_t dst, const void* src) {
    asm volatile("cp.async.cg.shared.global [%0], [%1], 16;" :: "r"(dst), "l"(src));
}
#define CP_COMMIT() asm volatile("cp.async.commit_group;" ::: "memory")
#define CP_WAIT2() asm volatile("cp.async.wait_group 2;" ::: "memory")
#define CP_WAIT1() asm volatile("cp.async.wait_group 1;" ::: "memory")
#define CP_WAIT0() asm volatile("cp.async.wait_group 0;" ::: "memory")

__device__ __forceinline__ void ldsm_x4(uint32_t* r, uint32_t addr) {
    asm volatile("ldmatrix.sync.aligned.m8n8.x4.shared.b16 {%0,%1,%2,%3}, [%4];"
        : "=r"(r[0]), "=r"(r[1]), "=r"(r[2]), "=r"(r[3]) : "r"(addr));
}
__device__ __forceinline__ void ldsm_x4_t(uint32_t* r, uint32_t addr) {
    asm volatile("ldmatrix.sync.aligned.m8n8.x4.trans.shared.b16 {%0,%1,%2,%3}, [%4];"
        : "=r"(r[0]), "=r"(r[1]), "=r"(r[2]), "=r"(r[3]) : "r"(addr));
}
__device__ __forceinline__ void mma_f16(float* d, const uint32_t* a, const uint32_t* b) {
    asm volatile(
        "mma.sync.aligned.m16n8k16.row.col.f32.f16.f16.f32 "
        "{%0,%1,%2,%3}, {%4,%5,%6,%7}, {%8,%9}, {%0,%1,%2,%3};"
        : "+f"(d[0]), "+f"(d[1]), "+f"(d[2]), "+f"(d[3])
        : "r"(a[0]), "r"(a[1]), "r"(a[2]), "r"(a[3]), "r"(b[0]), "r"(b[1]));
}
__device__ __forceinline__ uint32_t pack_h2(float a, float b) {
    half2 h = __floats2half2_rn(a, b);
    return *(uint32_t*)&h;
}
__device__ __forceinline__ float siluf(float x) { return x / (1.f + expf(-x)); }

// ---------------- fp16 mma GEMM (128x128 CTA, 8 warps 64x32, K-stage 32, 4-deep pipe,
//                  ONE __syncthreads per stage; optional dual-pass gate+up) -------------
// EPI: 0 none, 1 +bias[z*2048+col] (X), 2 +resid (X), 4 acc*Xr[z*S+row],
//      5 sigmoid(Xr[row])*acc + X[row*ldc+col].
// OUTH: half out. IDX: 0 none, 1 gather A via glist+bound, 2 bound only.
// ROPE: for z<2, rotate (d,d+64) per head in-epilogue. DUAL: pass1 B, pass2 B2,
// output silu(pass1)*pass2.
#define A_ELT 5120
#define B_ELT 4352
#define SMEM_BASE (4 * (A_ELT + B_ELT) * 2)
#define SMEM_DUAL (SMEM_BASE + 256 * 32 * 4)

template <int EPI, bool OUTH, int IDX, bool ROPE, bool DUAL>
__global__ void __launch_bounds__(256, 2)
hgemm(const __half* __restrict__ A, const __half* __restrict__ B,
      const __half* __restrict__ B2,
      void* __restrict__ Cv, const float* __restrict__ X, const float* __restrict__ Xr,
      const int* __restrict__ glist, const int* __restrict__ cnt,
      int K, int lda, int ldb, int ldc,
      long long sA, long long sB, long long sC) {
    int cbound = 0x7fffffff;
    if (IDX) {
        cbound = cnt[blockIdx.z];
        if ((int)blockIdx.y * 128 >= cbound) return;
    }
    extern __shared__ __half dsm[];
    __half* const AS = dsm;
    __half* const BS = dsm + 4 * A_ELT;
    __shared__ float s_inv[64];

    int tid = threadIdx.x, lane = tid & 31, wid = tid >> 5;
    int row0 = blockIdx.y * 128, col0 = blockIdx.x * 128;

    if (ROPE && tid < 64)
        s_inv[tid] = (float)exp(-((double)(2 * tid) / 128.0) * 13.815510557964274);

    A += (long long)blockIdx.z * sA;
    if (IDX != 1) A += (long long)row0 * lda;
    const __half* Bp = B + (long long)blockIdx.z * sB + col0;
    const __half* B2p = DUAL ? B2 + (long long)blockIdx.z * sB + col0 : (const __half*)0;

    int nstg = K >> 5;

    int arow = tid >> 2, acol = (tid & 3) * 8;
    int nrow = tid >> 4, ncol = (tid & 15) * 8;

    const __half* aptr[2];
#pragma unroll
    for (int i = 0; i < 2; i++) {
        int r = arow + i * 64;
        if (IDX == 1) {
            int gr = row0 + r;
            int ti = glist[blockIdx.z * S + (gr < cbound ? gr : 0)];
            aptr[i] = A + (long long)ti * lda;
        } else {
            aptr[i] = A + (long long)r * lda;
        }
    }

    const __half* Bcur = Bp;
    auto fill = [&](int s, int k0) {
        __half* ad = AS + s * A_ELT;
        __half* bd = BS + s * B_ELT;
#pragma unroll
        for (int i = 0; i < 2; i++)
            cp16(smem_u32(ad + (arow + i * 64) * 40 + acol), aptr[i] + k0 + acol);
#pragma unroll
        for (int i = 0; i < 2; i++)
            cp16(smem_u32(bd + (nrow + i * 16) * 136 + ncol),
                 Bcur + (long long)(k0 + nrow + i * 16) * ldb + ncol);
        CP_COMMIT();
    };

    float acc[4][4][4];
#pragma unroll
    for (int i = 0; i < 4; i++)
#pragma unroll
        for (int j = 0; j < 4; j++)
#pragma unroll
            for (int u = 0; u < 4; u++) acc[i][j][u] = 0.f;

    int wm = (wid & 1) * 64, wn = (wid >> 1) * 32;
    int fr = lane >> 2, fc = lane & 3;
    int l15 = lane & 15, lhi = (lane >> 4) << 3;

    uint32_t* stash = (uint32_t*)(dsm + SMEM_BASE / 2) + tid * 32;

    int npass = DUAL ? 2 : 1;
    for (int pass = 0; pass < npass; pass++) {
        if (pass == 1) Bcur = B2p;
        fill(0, 0);
        if (nstg > 1) fill(1, 32);
        if (nstg > 2) fill(2, 64);
        for (int t = 0; t < nstg; t++) {
            if (t + 2 < nstg) CP_WAIT2();
            else if (t + 1 < nstg) CP_WAIT1();
            else CP_WAIT0();
            __syncthreads();
            if (t + 3 < nstg) fill((t + 3) & 3, (t + 3) * 32);
            const __half* as = AS + (t & 3) * A_ELT;
            const __half* bs = BS + (t & 3) * B_ELT;
#pragma unroll
            for (int kk = 0; kk < 32; kk += 16) {
                uint32_t af[4][4];
#pragma unroll
                for (int mt = 0; mt < 4; mt++)
                    ldsm_x4(af[mt], smem_u32(as + (wm + mt * 16 + l15) * 40 + kk + lhi));
                uint32_t bf[4][2];
#pragma unroll
                for (int p = 0; p < 2; p++) {
                    uint32_t tmp[4];
                    ldsm_x4_t(tmp, smem_u32(bs + (kk + l15) * 136 + wn + p * 16 + lhi));
                    bf[2 * p][0] = tmp[0]; bf[2 * p][1] = tmp[1];
                    bf[2 * p + 1][0] = tmp[2]; bf[2 * p + 1][1] = tmp[3];
                }
#pragma unroll
                for (int mt = 0; mt < 4; mt++)
#pragma unroll
                    for (int nt = 0; nt < 4; nt++) mma_f16(acc[mt][nt], af[mt], bf[nt]);
            }
        }
        if (DUAL && pass == 0) {
#pragma unroll
            for (int mt = 0; mt < 4; mt++)
#pragma unroll
                for (int nt = 0; nt < 4; nt++) {
                    stash[(mt * 4 + nt) * 2] = pack_h2(acc[mt][nt][0], acc[mt][nt][1]);
                    stash[(mt * 4 + nt) * 2 + 1] = pack_h2(acc[mt][nt][2], acc[mt][nt][3]);
                    acc[mt][nt][0] = acc[mt][nt][1] = acc[mt][nt][2] = acc[mt][nt][3] = 0.f;
                }
            __syncthreads();
        }
    }

    bool doRope = ROPE && (blockIdx.z < 2);
    if (doRope) __syncthreads();

#pragma unroll
    for (int mt = 0; mt < 4; mt++) {
        int m = row0 + wm + mt * 16 + fr;
        float w0 = 1.f, w1 = 1.f;
        if (EPI == 4) {
            bool ok0 = (!IDX || m < cbound), ok1 = (!IDX || m + 8 < cbound);
            w0 = ok0 ? Xr[(long long)blockIdx.z * S + m] : 0.f;
            w1 = ok1 ? Xr[(long long)blockIdx.z * S + m + 8] : 0.f;
        }
        if (EPI == 5) {
            w0 = 1.f / (1.f + expf(-Xr[m]));
            w1 = 1.f / (1.f + expf(-Xr[m + 8]));
        }
#pragma unroll
        for (int nt = 0; nt < 4; nt++) {
            int nl = wn + nt * 8 + fc * 2;
            int n = col0 + nl;
            float2 v0 = make_float2(acc[mt][nt][0], acc[mt][nt][1]);
            float2 v1 = make_float2(acc[mt][nt][2], acc[mt][nt][3]);
            if (EPI == 1) {
                const float* bz = X + (long long)blockIdx.z * 2048;
                v0.x += bz[n]; v0.y += bz[n + 1];
                v1.x += bz[n]; v1.y += bz[n + 1];
            }
            if (EPI == 2) {
                const float2 r0 = *(const float2*)&X[(long long)m * ldc + n];
                const float2 r1 = *(const float2*)&X[(long long)(m + 8) * ldc + n];
                v0.x += r0.x; v0.y += r0.y;
                v1.x += r1.x; v1.y += r1.y;
            }
            if (DUAL) {
                half2 g0 = *(half2*)&stash[(mt * 4 + nt) * 2];
                half2 g1 = *(half2*)&stash[(mt * 4 + nt) * 2 + 1];
                v0.x *= siluf(__half2float(g0.x));
                v0.y *= siluf(__half2float(g0.y));
                v1.x *= siluf(__half2float(g1.x));
                v1.y *= siluf(__half2float(g1.y));
            }
            if (EPI == 4) {
                v0.x *= w0; v0.y *= w0;
                v1.x *= w1; v1.y *= w1;
            }
            if (EPI == 5) {
                const float2 r0 = *(const float2*)&X[(long long)m * ldc + n];
                const float2 r1 = *(const float2*)&X[(long long)(m + 8) * ldc + n];
                v0.x = v0.x * w0 + r0.x; v0.y = v0.y * w0 + r0.y;
                v1.x = v1.x * w1 + r1.x; v1.y = v1.y * w1 + r1.y;
            }
            if (doRope) {
                int rl0 = wm + mt * 16 + fr;
                *(half2*)&dsm[rl0 * 136 + nl] = __floats2half2_rn(v0.x, v0.y);
                *(half2*)&dsm[(rl0 + 8) * 136 + nl] = __floats2half2_rn(v1.x, v1.y);
            } else if (OUTH) {
                __half* C = (__half*)Cv + (long long)blockIdx.z * sC;
                if (!IDX || m < cbound)
                    *(half2*)&C[(long long)m * ldc + n] = __floats2half2_rn(v0.x, v0.y);
                if (!IDX || m + 8 < cbound)
                    *(half2*)&C[(long long)(m + 8) * ldc + n] = __floats2half2_rn(v1.x, v1.y);
            } else {
                float* C = (float*)Cv + (long long)blockIdx.z * sC;
                if (!IDX || m < cbound)
                    *(float2*)&C[(long long)m * ldc + n] = v0;
                if (!IDX || m + 8 < cbound)
                    *(float2*)&C[(long long)(m + 8) * ldc + n] = v1;
            }
        }
    }

    if (doRope) {
        __syncthreads();
        __half* C = (__half*)Cv + (long long)blockIdx.z * sC;
        for (int it = tid; it < 128 * 64; it += 256) {
            int row = it >> 6, d = it & 63;
            int sg = row0 + row;
            float ang = (float)sg * s_inv[d];
            float cc = cosf(ang), ssn = sinf(ang);
            float a = __half2float(dsm[row * 136 + d]);
            float b = __half2float(dsm[row * 136 + d + 64]);
            C[(long long)sg * ldc + col0 + d] = __float2half_rn(a * cc - b * ssn);
            C[(long long)sg * ldc + col0 + d + 64] = __float2half_rn(b * cc + a * ssn);
        }
    }
}

// ---------------- flash attention (Q fragments hoisted to registers) ----------------
#define FSC 0.12751744f
__global__ void __launch_bounds__(256, 1)
flash_kernel(const __half* __restrict__ Q, const __half* __restrict__ K,
             const __half* __restrict__ V, __half* __restrict__ O) {
    int qb = 15 - (int)blockIdx.x;
    int h = blockIdx.y;
    extern __shared__ __half fsm[];
    __half* Ks = fsm;                    // [2][128][136]
    __half* Vs = fsm + 2 * 128 * 136;    // [2][128][136]

    int tid = threadIdx.x, lane = tid & 31, wid = tid >> 5;
    int fr = lane >> 2, fc = lane & 3;
    int l15 = lane & 15, lhi = (lane >> 4) << 3;
    int wm = wid * 16;

    const __half* qg = Q + (long long)(qb * 128) * H + h * D;
    const __half* kg = K + h * D;
    const __half* vg = V + h * D;

    int lr = tid >> 1, lc = (tid & 1) * 64;

    // stage Q into Ks buf0, load fragments to registers, then release
#pragma unroll
    for (int j = 0; j < 8; j++)
        cp16(smem_u32(Ks + lr * 136 + lc + j * 8), qg + (long long)lr * H + lc + j * 8);
    CP_COMMIT();
    CP_WAIT0();
    __syncthreads();
    uint32_t qf[8][4];
#pragma unroll
    for (int kk = 0; kk < 8; kk++)
        ldsm_x4(qf[kk], smem_u32(Ks + (wm + l15) * 136 + kk * 16 + lhi));
    __syncthreads();

    auto loadKV = [&](int buf, int kt) {
        const __half* ks = kg + (long long)(kt * 128) * H;
        const __half* vs = vg + (long long)(kt * 128) * H;
        __half* kd = Ks + buf * (128 * 136);
        __half* vd = Vs + buf * (128 * 136);
#pragma unroll
        for (int j = 0; j < 8; j++) {
            cp16(smem_u32(kd + lr * 136 + lc + j * 8), ks + (long long)lr * H + lc + j * 8);
            cp16(smem_u32(vd + lr * 136 + lc + j * 8), vs + (long long)lr * H + lc + j * 8);
        }
    };
    loadKV(0, 0); CP_COMMIT();

    float oacc[16][4];
#pragma unroll
    for (int i = 0; i < 16; i++)
#pragma unroll
        for (int u = 0; u < 4; u++) oacc[i][u] = 0.f;
    float m0 = -1e30f, m1 = -1e30f, l0 = 0.f, l1 = 0.f;

    int ntile = qb + 1;
    for (int t = 0; t < ntile; t++) {
        if (t + 1 < ntile) { loadKV((t + 1) & 1, t + 1); CP_COMMIT(); CP_WAIT1(); }
        else CP_WAIT0();
        __syncthreads();
        const __half* kb = Ks + (t & 1) * (128 * 136);
        const __half* vb = Vs + (t & 1) * (128 * 136);

        float s[16][4];
#pragma unroll
        for (int i = 0; i < 16; i++)
#pragma unroll
            for (int u = 0; u < 4; u++) s[i][u] = 0.f;

#pragma unroll
        for (int kk = 0; kk < 8; kk++) {
#pragma unroll
            for (int nt = 0; nt < 16; nt++) {
                uint32_t bk[2];
                bk[0] = *(const uint32_t*)(kb + (nt * 8 + fr) * 136 + kk * 16 + 2 * fc);
                bk[1] = *(const uint32_t*)(kb + (nt * 8 + fr) * 136 + kk * 16 + 2 * fc + 8);
                mma_f16(s[nt], qf[kk], bk);
            }
        }

        if (t == qb) {
            int r0 = wm + fr, r1 = r0 + 8;
#pragma unroll
            for (int nt = 0; nt < 16; nt++) {
                int c0 = nt * 8 + 2 * fc;
                if (c0 > r0) s[nt][0] = -1e30f;
                if (c0 + 1 > r0) s[nt][1] = -1e30f;
                if (c0 > r1) s[nt][2] = -1e30f;
                if (c0 + 1 > r1) s[nt][3] = -1e30f;
            }
        }

        float mx0 = -1e30f, mx1 = -1e30f;
#pragma unroll
        for (int nt = 0; nt < 16; nt++) {
            mx0 = fmaxf(mx0, fmaxf(s[nt][0], s[nt][1]));
            mx1 = fmaxf(mx1, fmaxf(s[nt][2], s[nt][3]));
        }
        mx0 = fmaxf(mx0, __shfl_xor_sync(0xffffffffu, mx0, 1));
        mx0 = fmaxf(mx0, __shfl_xor_sync(0xffffffffu, mx0, 2));
        mx1 = fmaxf(mx1, __shfl_xor_sync(0xffffffffu, mx1, 1));
        mx1 = fmaxf(mx1, __shfl_xor_sync(0xffffffffu, mx1, 2));

        float mn0 = fmaxf(m0, mx0), mn1 = fmaxf(m1, mx1);
        float rs0 = exp2f((m0 - mn0) * FSC), rs1 = exp2f((m1 - mn1) * FSC);
        m0 = mn0; m1 = mn1;

        float sm0 = 0.f, sm1 = 0.f;
#pragma unroll
        for (int nt = 0; nt < 16; nt++) {
            s[nt][0] = exp2f((s[nt][0] - m0) * FSC);
            s[nt][1] = exp2f((s[nt][1] - m0) * FSC);
            s[nt][2] = exp2f((s[nt][2] - m1) * FSC);
            s[nt][3] = exp2f((s[nt][3] - m1) * FSC);
            sm0 += s[nt][0] + s[nt][1];
            sm1 += s[nt][2] + s[nt][3];
        }
        sm0 += __shfl_xor_sync(0xffffffffu, sm0, 1);
        sm0 += __shfl_xor_sync(0xffffffffu, sm0, 2);
        sm1 += __shfl_xor_sync(0xffffffffu, sm1, 1);
        sm1 += __shfl_xor_sync(0xffffffffu, sm1, 2);
        l0 = l0 * rs0 + sm0;
        l1 = l1 * rs1 + sm1;
#pragma unroll
        for (int nt = 0; nt < 16; nt++) {
            oacc[nt][0] *= rs0; oacc[nt][1] *= rs0;
            oacc[nt][2] *= rs1; oacc[nt][3] *= rs1;
        }

#pragma unroll
        for (int kc = 0; kc < 8; kc++) {
            uint32_t pa[4];
            pa[0] = pack_h2(s[2 * kc][0], s[2 * kc][1]);
            pa[1] = pack_h2(s[2 * kc][2], s[2 * kc][3]);
            pa[2] = pack_h2(s[2 * kc + 1][0], s[2 * kc + 1][1]);
            pa[3] = pack_h2(s[2 * kc + 1][2], s[2 * kc + 1][3]);
#pragma unroll
            for (int p = 0; p < 8; p++) {
                uint32_t tmp[4];
                ldsm_x4_t(tmp, smem_u32(vb + (kc * 16 + l15) * 136 + p * 16 + lhi));
                mma_f16(oacc[2 * p], pa, tmp);
                mma_f16(oacc[2 * p + 1], pa, tmp + 2);
            }
        }
        __syncthreads();
    }

    float inv0 = 1.f / l0, inv1 = 1.f / l1;
    __half* og = O + (long long)(qb * 128) * H + h * D;
    int r0 = wm + fr, r1 = r0 + 8;
#pragma unroll
    for (int nt = 0; nt < 16; nt++) {
        int col = nt * 8 + 2 * fc;
        *(half2*)(og + (long long)r0 * H + col) =
            __floats2half2_rn(oacc[nt][0] * inv0, oacc[nt][1] * inv0);
        *(half2*)(og + (long long)r1 * H + col) =
            __floats2half2_rn(oacc[nt][2] * inv1, oacc[nt][3] * inv1);
    }
}
#define FLASH_SMEM (4 * 128 * 136 * 2)

// ---------------- fp32 -> fp16 (2x float4 per thread per iter) ----------------
__global__ void f2h_kernel(const float* __restrict__ in, __half* __restrict__ out, long long n) {
    long long i = ((long long)blockIdx.x * 256 + threadIdx.x) * 8;
    long long stride = (long long)gridDim.x * 2048;
    for (; i + 7 < n; i += stride) {
        float4 a = *(const float4*)&in[i];
        float4 b = *(const float4*)&in[i + 4];
        *(half2*)&out[i] = __floats2half2_rn(a.x, a.y);
        *(half2*)&out[i + 2] = __floats2half2_rn(a.z, a.w);
        *(half2*)&out[i + 4] = __floats2half2_rn(b.x, b.y);
        *(half2*)&out[i + 6] = __floats2half2_rn(b.z, b.w);
    }
}
static inline unsigned f2h_grid(long long n) {
    long long g = (n / 8 + 255) / 256;
    return (unsigned)(g > 4096 ? 4096 : g);
}

// ---------------- pack 3 bias vectors ----------------
__global__ void bcopy_kernel(const float* a, const float* b, const float* c, float* o) {
    int i = blockIdx.x * 1024 + threadIdx.x;
    const float* src[3] = {a, b, c};
    o[i] = src[i >> 11][i & 2047];
}

// ---------------- RMSNorm ----------------
__global__ void rmsnorm_kernel(const float* __restrict__ x, const float* __restrict__ w,
                               __half* __restrict__ oh, float* __restrict__ of,
                               int* __restrict__ zcnt) {
    int s = blockIdx.x;
    if (zcnt && s == 0 && threadIdx.x < NE) zcnt[threadIdx.x] = 0;
    const float* xr = x + (long long)s * H;
    int tid = threadIdx.x;
    float ss = 0.f;
    for (int i = tid; i < H; i += 256) { float v = xr[i]; ss += v * v; }
    __shared__ float sh[8];
#pragma unroll
    for (int off = 16; off; off >>= 1) ss += __shfl_xor_sync(0xffffffffu, ss, off);
    if ((tid & 31) == 0) sh[tid >> 5] = ss;
    __syncthreads();
    ss = sh[tid & 7];
#pragma unroll
    for (int off = 4; off; off >>= 1) ss += __shfl_xor_sync(0xffffffffu, ss, off);
    float inv = rsqrtf(ss / (float)H + 1e-6f);
    for (int i = tid; i < H; i += 256) {
        float v = w[i] * xr[i] * inv;
        oh[(long long)s * H + i] = __float2half_rn(v);
        if (of) of[(long long)s * H + i] = v;
    }
}

// ---------------- router + top-k compaction ----------------
__global__ void router_kernel(const float* __restrict__ h2, const float* __restrict__ gw,
                              const float* __restrict__ sgate, float* __restrict__ rl,
                              float* __restrict__ sgl, int* __restrict__ cnt,
                              int* __restrict__ glist, int* __restrict__ slot,
                              float* __restrict__ wsl) {
    int s = blockIdx.x;
    int tid = threadIdx.x;
    const float* hr = h2 + (long long)s * H;
    float acc[9];
#pragma unroll
    for (int j = 0; j < 9; j++) acc[j] = 0.f;
    for (int i = tid; i < H; i += 256) {
        float hv = hr[i];
        const float* gr = gw + (long long)i * NE;
#pragma unroll
        for (int e = 0; e < NE; e++) acc[e] += hv * gr[e];
        acc[8] += hv * sgate[i];
    }
    __shared__ float sh[8][9];
    int warp = tid >> 5, lane = tid & 31;
#pragma unroll
    for (int j = 0; j < 9; j++) {
        float v = acc[j];
#pragma unroll
        for (int o = 16; o; o >>= 1) v += __shfl_xor_sync(0xffffffffu, v, o);
        if (lane == 0) sh[warp][j] = v;
    }
    __syncthreads();
    if (tid == 0) {
        float t[9];
#pragma unroll
        for (int j = 0; j < 9; j++) {
            float v = 0.f;
            for (int wi = 0; wi < 8; wi++) v += sh[wi][j];
            t[j] = v;
        }
        float mx = t[0];
        for (int e = 1; e < NE; e++) mx = fmaxf(mx, t[e]);
        float p[NE], sum = 0.f;
        for (int e = 0; e < NE; e++) { p[e] = expf(t[e] - mx); sum += p[e]; }
        for (int e = 0; e < NE; e++) p[e] /= sum;
        for (int kI = 0; kI < TOPK; kI++) {
            int bi = 0;
            float bv = p[0];
            for (int e = 1; e < NE; e++)
                if (p[e] > bv) { bv = p[e]; bi = e; }
            int pos = atomicAdd(&cnt[bi], 1);
            glist[bi * S + pos] = s;
            slot[s * TOPK + kI] = bi * S + pos;
            wsl[bi * S + pos] = bv;
            p[bi] = -1.f;
        }
        for (int e = 0; e < NE; e++) rl[s * NE + e] = t[e];
        sgl[s] = t[8];
    }
}

// ---------------- final combine: out = sm + sum_k eoh[slot_k] ----------------
__global__ void final_kernel(const __half* __restrict__ eoh, const int* __restrict__ slot,
                             const float* __restrict__ sm, float* __restrict__ out) {
    int i = (blockIdx.x * 256 + threadIdx.x) * 2;
    int s = i >> 11, c = i & 2047;
    float mx = 0.f, my = 0.f;
#pragma unroll
    for (int kI = 0; kI < TOPK; kI++) {
        half2 v = *(const half2*)&eoh[(long long)slot[s * TOPK + kI] * H + c];
        mx += __half2float(v.x);
        my += __half2float(v.y);
    }
    float2 sv = *(const float2*)&sm[i];
    float2 o = make_float2(sv.x + mx, sv.y + my);
    *(float2*)&out[i] = o;
}

// ---------------- host ----------------
extern "C" void kernel_launch(void* const* d_in, const int* in_sizes, int n_in,
                              void* d_out, int out_size) {
    const float* x = (const float*)d_in[0];
    const float* ln1 = (const float*)d_in[1];
    const float* ln2 = (const float*)d_in[2];
    const float* wq = (const float*)d_in[3];
    const float* bq = (const float*)d_in[4];
    const float* wk = (const float*)d_in[5];
    const float* bk = (const float*)d_in[6];
    const float* wv = (const float*)d_in[7];
    const float* bv = (const float*)d_in[8];
    const float* wo = (const float*)d_in[9];
    const float* gw = (const float*)d_in[10];
    const float* eg = (const float*)d_in[11];
    const float* eu = (const float*)d_in[12];
    const float* ed = (const float*)d_in[13];
    const float* sg = (const float*)d_in[14];
    const float* su = (const float*)d_in[15];
    const float* sd = (const float*)d_in[16];
    const float* sgate = (const float*)d_in[17];
    float* out = (float*)d_out;

    float *x2, *h2f, *sm, *sgl, *rls, *wsl, *bqkv;
    int *cnt, *glist, *slot;
    __half *h1h, *qkvh, *ath, *h2h, *uhh, *eoh, *ssh;
    __half *wqkvh, *woh, *egh, *euh, *edh, *sgw, *suw, *sdw;
    cudaGetSymbolAddress((void**)&x2, g_x2);
    cudaGetSymbolAddress((void**)&h2f, g_h2f);
    cudaGetSymbolAddress((void**)&sm, g_sm);
    cudaGetSymbolAddress((void**)&sgl, g_sgl);
    cudaGetSymbolAddress((void**)&rls, g_rl);
    cudaGetSymbolAddress((void**)&wsl, g_wsl);
    cudaGetSymbolAddress((void**)&bqkv, g_bqkv);
    cudaGetSymbolAddress((void**)&cnt, g_cnt);
    cudaGetSymbolAddress((void**)&glist, g_glist);
    cudaGetSymbolAddress((void**)&slot, g_slot);
    cudaGetSymbolAddress((void**)&h1h, g_h1h);
    cudaGetSymbolAddress((void**)&qkvh, g_qkvh);
    cudaGetSymbolAddress((void**)&ath, g_ath);
    cudaGetSymbolAddress((void**)&h2h, g_h2h);
    cudaGetSymbolAddress((void**)&uhh, g_uhh);
    cudaGetSymbolAddress((void**)&eoh, g_eoh);
    cudaGetSymbolAddress((void**)&ssh, g_ssh);
    cudaGetSymbolAddress((void**)&wqkvh, g_wqkvh);
    cudaGetSymbolAddress((void**)&woh, g_woh);
    cudaGetSymbolAddress((void**)&egh, g_egh);
    cudaGetSymbolAddress((void**)&euh, g_euh);
    cudaGetSymbolAddress((void**)&edh, g_edh);
    cudaGetSymbolAddress((void**)&sgw, g_sgw);
    cudaGetSymbolAddress((void**)&suw, g_suw);
    cudaGetSymbolAddress((void**)&sdw, g_sdw);

    __half* qh = qkvh;
    __half* kh = qkvh + (long long)S * H;
    __half* vh = qkvh + (long long)2 * S * H;

    cudaFuncSetAttribute(flash_kernel, cudaFuncAttributeMaxDynamicSharedMemorySize, FLASH_SMEM);
    cudaFuncSetAttribute(hgemm<1, true, 0, true, false>, cudaFuncAttributeMaxDynamicSharedMemorySize, SMEM_BASE);
    cudaFuncSetAttribute(hgemm<2, false, 0, false, false>, cudaFuncAttributeMaxDynamicSharedMemorySize, SMEM_BASE);
    cudaFuncSetAttribute(hgemm<0, true, 1, false, true>, cudaFuncAttributeMaxDynamicSharedMemorySize, SMEM_DUAL);
    cudaFuncSetAttribute(hgemm<4, true, 2, false, false>, cudaFuncAttributeMaxDynamicSharedMemorySize, SMEM_BASE);
    cudaFuncSetAttribute(hgemm<0, true, 0, false, true>, cudaFuncAttributeMaxDynamicSharedMemorySize, SMEM_DUAL);
    cudaFuncSetAttribute(hgemm<5, false, 0, false, false>, cudaFuncAttributeMaxDynamicSharedMemorySize, SMEM_BASE);

    static cudaStream_t s2 = 0, s3 = 0;
    static cudaEvent_t evFork = 0, evW0 = 0, evWm = 0, evWd = 0, evWs = 0, evW = 0,
                       evH2 = 0, evRt = 0, evSh = 0, evN = 0;
    if (!s2) {
        cudaStreamCreateWithFlags(&s2, cudaStreamNonBlocking);
        cudaStreamCreateWithFlags(&s3, cudaStreamNonBlocking);
        cudaEventCreateWithFlags(&evFork, cudaEventDisableTiming);
        cudaEventCreateWithFlags(&evW0, cudaEventDisableTiming);
        cudaEventCreateWithFlags(&evWm, cudaEventDisableTiming);
        cudaEventCreateWithFlags(&evWd, cudaEventDisableTiming);
        cudaEventCreateWithFlags(&evWs, cudaEventDisableTiming);
        cudaEventCreateWithFlags(&evW, cudaEventDisableTiming);
        cudaEventCreateWithFlags(&evH2, cudaEventDisableTiming);
        cudaEventCreateWithFlags(&evRt, cudaEventDisableTiming);
        cudaEventCreateWithFlags(&evSh, cudaEventDisableTiming);
        cudaEventCreateWithFlags(&evN, cudaEventDisableTiming);
    }

    float* rl_dst = (out_size >= S * H + S * NE) ? (out + (size_t)S * H) : rls;

    // ---- fork conversion stream, ordered by consumer time ----
    cudaEventRecord(evFork, 0);
    cudaStreamWaitEvent(s2, evFork, 0);
    bcopy_kernel<<<6, 1024, 0, s2>>>(bq, bk, bv, bqkv);
    f2h_kernel<<<f2h_grid((long long)H * H), 256, 0, s2>>>(wq, wqkvh, (long long)H * H);
    f2h_kernel<<<f2h_grid((long long)H * H), 256, 0, s2>>>(wk, wqkvh + (long long)H * H, (long long)H * H);
    f2h_kernel<<<f2h_grid((long long)H * H), 256, 0, s2>>>(wv, wqkvh + (long long)2 * H * H, (long long)H * H);
    cudaEventRecord(evW0, s2);
    f2h_kernel<<<f2h_grid((long long)H * H), 256, 0, s2>>>(wo, woh, (long long)H * H);
    f2h_kernel<<<4096, 256, 0, s2>>>(eg, egh, (long long)NE * H * IE);
    f2h_kernel<<<4096, 256, 0, s2>>>(eu, euh, (long long)NE * H * IE);
    cudaEventRecord(evWm, s2);
    f2h_kernel<<<4096, 256, 0, s2>>>(ed, edh, (long long)NE * IE * H);
    cudaEventRecord(evWd, s2);
    f2h_kernel<<<4096, 256, 0, s2>>>(sg, sgw, (long long)H * IS);
    f2h_kernel<<<4096, 256, 0, s2>>>(su, suw, (long long)H * IS);
    cudaEventRecord(evWs, s2);
    f2h_kernel<<<4096, 256, 0, s2>>>(sd, sdw, (long long)IS * H);
    cudaEventRecord(evW, s2);

    // ---- rmsnorm1 on s3 concurrent with f2h ----
    cudaStreamWaitEvent(s3, evFork, 0);
    rmsnorm_kernel<<<S, 256, 0, s3>>>(x, ln1, h1h, (float*)0, (int*)0);
    cudaEventRecord(evN, s3);

    // ---- main stream: attention path ----
    cudaStreamWaitEvent(0, evW0, 0);
    cudaStreamWaitEvent(0, evN, 0);
    hgemm<1, true, 0, true, false><<<dim3(16, 16, 3), 256, SMEM_BASE>>>(
        h1h, wqkvh, (const __half*)0, qkvh, bqkv, (const float*)0, 0, 0,
        H, H, H, H, 0LL, (long long)H * H, (long long)S * H);
    flash_kernel<<<dim3(16, NH), 256, FLASH_SMEM>>>(qh, kh, vh, ath);
    hgemm<2, false, 0, false, false><<<dim3(16, 16, 1), 256, SMEM_BASE>>>(
        ath, woh, (const __half*)0, x2, x, (const float*)0, 0, 0, H, H, H, H, 0, 0, 0);
    rmsnorm_kernel<<<S, 256>>>(x2, ln2, h2h, h2f, cnt);
    cudaEventRecord(evH2, 0);
    router_kernel<<<S, 256>>>(h2f, gw, sgate, rl_dst, sgl, cnt, glist, slot, wsl);
    cudaEventRecord(evRt, 0);

    // ---- stream s3: shared MLP branch (dual gate+up, then fused down) ----
    cudaStreamWaitEvent(s3, evH2, 0);
    cudaStreamWaitEvent(s3, evWs, 0);
    hgemm<0, true, 0, false, true><<<dim3(IS / 128, 16, 1), 256, SMEM_DUAL, s3>>>(
        h2h, sgw, suw, ssh, (const float*)0, (const float*)0, 0, 0, H, H, IS, IS, 0, 0, 0);
    cudaStreamWaitEvent(s3, evW, 0);
    cudaStreamWaitEvent(s3, evRt, 0);
    hgemm<5, false, 0, false, false><<<dim3(16, 16, 1), 256, SMEM_BASE, s3>>>(
        ssh, sdw, (const __half*)0, sm, x2, sgl, 0, 0, IS, IS, H, H, 0, 0, 0);
    cudaEventRecord(evSh, s3);

    // ---- main stream: sparse MoE branch (dual gate+up, then weighted down) ----
    cudaStreamWaitEvent(0, evWm, 0);
    hgemm<0, true, 1, false, true><<<dim3(IE / 128, 16, NE), 256, SMEM_DUAL>>>(
        h2h, egh, euh, uhh, (const float*)0, (const float*)0, glist, cnt,
        H, H, IE, IE, 0LL, (long long)H * IE, (long long)S * IE);
    cudaStreamWaitEvent(0, evWd, 0);
    hgemm<4, true, 2, false, false><<<dim3(16, 16, NE), 256, SMEM_BASE>>>(
        uhh, edh, (const __half*)0, eoh, (const float*)0, wsl, (const int*)0, cnt,
        IE, IE, H, H, (long long)S * IE, (long long)IE * H, (long long)S * H);

    // ---- join + combine ----
    cudaStreamWaitEvent(0, evSh, 0);
    final_kernel<<<(S * H) / 512, 256>>>(eoh, slot, sm, out);
}